// round 1
// baseline (speedup 1.0000x reference)
#include <cuda_runtime.h>
#include <cstdint>
#include <cstddef>

#define BB    64
#define TT    20
#define EMBD  512
#define VOC   32000
#define NSTEP 19
#define GDIM  2048
#define KSPLIT 4

// ---------------- scratch (no allocations allowed) ----------------
__device__ float g_embsteps[NSTEP * BB * EMBD];   // [t][b][e], t = 0..18
__device__ float g_seq[BB * TT * EMBD];           // [b][t][e]: col0 = emb, cols 1..19 = h
__device__ float g_xpre[NSTEP * BB * GDIM];       // [t][b][4E]
__device__ float g_part[KSPLIT * BB * GDIM];      // k-split partials of h @ W_hh^T
__device__ float g_h[BB * EMBD];
__device__ float g_c[BB * EMBD];

// ---------------- helpers ----------------
__device__ __forceinline__ unsigned f2tf(float x) {
    unsigned u;
    asm("cvt.rna.tf32.f32 %0, %1;" : "=r"(u) : "f"(x));
    return u;
}

__device__ __forceinline__ void mma8(float c[4], const unsigned a[4], const unsigned b[2]) {
    asm volatile(
        "mma.sync.aligned.m16n8k8.row.col.f32.tf32.tf32.f32 "
        "{%0,%1,%2,%3}, {%4,%5,%6,%7}, {%8,%9}, {%0,%1,%2,%3};"
        : "+f"(c[0]), "+f"(c[1]), "+f"(c[2]), "+f"(c[3])
        : "r"(a[0]), "r"(a[1]), "r"(a[2]), "r"(a[3]), "r"(b[0]), "r"(b[1]));
}

// ---------------- init: embedding gather + h0/c0 ----------------
__global__ void init_kernel(const float* __restrict__ features,
                            const int*   __restrict__ captions,
                            const float* __restrict__ W_emb) {
    int idx = blockIdx.x * blockDim.x + threadIdx.x;       // over B*T*(E/4)
    if (idx >= BB * TT * (EMBD / 4)) return;
    int e4 = idx & (EMBD / 4 - 1);
    int bt = idx >> 7;
    int t = bt % TT, b = bt / TT;
    int cap = captions[b * TT + t];
    float4 v = *(const float4*)(W_emb + (size_t)cap * EMBD + e4 * 4);
    if (t < NSTEP)
        *(float4*)(g_embsteps + ((size_t)(t * BB + b)) * EMBD + e4 * 4) = v;
    if (t == 0) {
        *(float4*)(g_seq + ((size_t)b * TT) * EMBD + e4 * 4) = v;          // seq[:,0] = emb
        *(float4*)(g_h + (size_t)b * EMBD + e4 * 4) = make_float4(0.f, 0.f, 0.f, 0.f);
        *(float4*)(g_c + (size_t)b * EMBD + e4 * 4) =
            *(const float4*)(features + (size_t)b * EMBD + e4 * 4);        // c0 = features
    }
}

// ---------------- TF32 tensor-core GEMM: C[M,N] = A[M,K] * B[N,K]^T (+bias) ----
// A, B row-major with row stride 512. NSPLIT=2 -> 3xTF32 (fp32-grade accuracy).
// blockIdx.z k-splits: consumes K columns starting at z*K, writes C + z*M*N.
template <int BM, int WM, int WN, int NSPLIT>
__global__ void __launch_bounds__(256)
gemm_tf32(const float* __restrict__ A, const float* __restrict__ B,
          float* __restrict__ C,
          const float* __restrict__ bias0, const float* __restrict__ bias1,
          int M, int N, int K) {
    constexpr int BN = 128, BK = 16;
    constexpr int WROWS = BM / WM;       // warp tile rows
    constexpr int WCOLS = BN / WN;       // warp tile cols
    constexpr int MT = WROWS / 16;
    constexpr int NT = WCOLS / 8;
    static_assert(WM * WN == 8, "8 warps");

    __shared__ float As[NSPLIT][BM][BK + 4];
    __shared__ float Bs[NSPLIT][BN][BK + 4];

    A += (size_t)blockIdx.z * K;
    B += (size_t)blockIdx.z * K;
    C += (size_t)blockIdx.z * M * N;

    const int tid  = threadIdx.x;
    const int lane = tid & 31, w = tid >> 5;
    const int wm = w / WN, wn = w % WN;
    const int r = lane >> 2, cq = lane & 3;

    float acc[MT][NT][4];
#pragma unroll
    for (int mi = 0; mi < MT; mi++)
#pragma unroll
        for (int ni = 0; ni < NT; ni++)
#pragma unroll
            for (int j = 0; j < 4; j++) acc[mi][ni][j] = 0.f;

    for (int k0 = 0; k0 < K; k0 += BK) {
        __syncthreads();
        // stage A tile (guard M), round (and split) to tf32
        for (int i = tid; i < BM * BK / 4; i += 256) {
            int row = i >> 2, kq = i & 3;
            int gm = blockIdx.y * BM + row;
            float4 v = make_float4(0.f, 0.f, 0.f, 0.f);
            if (gm < M) v = *(const float4*)(A + (size_t)gm * 512 + k0 + kq * 4);
            float xs[4] = {v.x, v.y, v.z, v.w};
#pragma unroll
            for (int j = 0; j < 4; j++) {
                float hi = __uint_as_float(f2tf(xs[j]));
                As[0][row][kq * 4 + j] = hi;
                if constexpr (NSPLIT == 2)
                    As[1][row][kq * 4 + j] = __uint_as_float(f2tf(xs[j] - hi));
            }
        }
        // stage B tile (N is a multiple of BN)
        for (int i = tid; i < BN * BK / 4; i += 256) {
            int row = i >> 2, kq = i & 3;
            int gn = blockIdx.x * BN + row;
            float4 v = *(const float4*)(B + (size_t)gn * 512 + k0 + kq * 4);
            float xs[4] = {v.x, v.y, v.z, v.w};
#pragma unroll
            for (int j = 0; j < 4; j++) {
                float hi = __uint_as_float(f2tf(xs[j]));
                Bs[0][row][kq * 4 + j] = hi;
                if constexpr (NSPLIT == 2)
                    Bs[1][row][kq * 4 + j] = __uint_as_float(f2tf(xs[j] - hi));
            }
        }
        __syncthreads();

#pragma unroll
        for (int kk = 0; kk < BK; kk += 8) {
            unsigned afh[MT][4], afl[MT][4];
#pragma unroll
            for (int mi = 0; mi < MT; mi++) {
                int mrow = wm * WROWS + mi * 16;
                afh[mi][0] = __float_as_uint(As[0][mrow + r][kk + cq]);
                afh[mi][1] = __float_as_uint(As[0][mrow + r + 8][kk + cq]);
                afh[mi][2] = __float_as_uint(As[0][mrow + r][kk + cq + 4]);
                afh[mi][3] = __float_as_uint(As[0][mrow + r + 8][kk + cq + 4]);
                if constexpr (NSPLIT == 2) {
                    afl[mi][0] = __float_as_uint(As[1][mrow + r][kk + cq]);
                    afl[mi][1] = __float_as_uint(As[1][mrow + r + 8][kk + cq]);
                    afl[mi][2] = __float_as_uint(As[1][mrow + r][kk + cq + 4]);
                    afl[mi][3] = __float_as_uint(As[1][mrow + r + 8][kk + cq + 4]);
                }
            }
#pragma unroll
            for (int ni = 0; ni < NT; ni++) {
                int ncol = wn * WCOLS + ni * 8;
                unsigned bh[2], bl[2];
                bh[0] = __float_as_uint(Bs[0][ncol + r][kk + cq]);
                bh[1] = __float_as_uint(Bs[0][ncol + r][kk + cq + 4]);
                if constexpr (NSPLIT == 2) {
                    bl[0] = __float_as_uint(Bs[1][ncol + r][kk + cq]);
                    bl[1] = __float_as_uint(Bs[1][ncol + r][kk + cq + 4]);
                }
#pragma unroll
                for (int mi = 0; mi < MT; mi++) {
                    mma8(acc[mi][ni], afh[mi], bh);
                    if constexpr (NSPLIT == 2) {
                        mma8(acc[mi][ni], afh[mi], bl);
                        mma8(acc[mi][ni], afl[mi], bh);
                    }
                }
            }
        }
    }

    // epilogue
#pragma unroll
    for (int mi = 0; mi < MT; mi++) {
        const int row0 = blockIdx.y * BM + wm * WROWS + mi * 16 + r;
#pragma unroll
        for (int ni = 0; ni < NT; ni++) {
            const int col = blockIdx.x * BN + wn * WCOLS + ni * 8 + 2 * cq;
            float b0 = 0.f, b1 = 0.f;
            if (bias0) { b0 += bias0[col]; b1 += bias0[col + 1]; }
            if (bias1) { b0 += bias1[col]; b1 += bias1[col + 1]; }
            if (row0 < M) {
                float2 o;
                o.x = acc[mi][ni][0] + b0;
                o.y = acc[mi][ni][1] + b1;
                *(float2*)(C + (size_t)row0 * N + col) = o;
            }
            if (row0 + 8 < M) {
                float2 o;
                o.x = acc[mi][ni][2] + b0;
                o.y = acc[mi][ni][3] + b1;
                *(float2*)(C + (size_t)(row0 + 8) * N + col) = o;
            }
        }
    }
}

// ---------------- LSTM cell pointwise: gates = xpre + sum(partials); update h,c ----
__global__ void cell_kernel(int s) {
    int idx = blockIdx.x * blockDim.x + threadIdx.x;
    if (idx >= BB * EMBD) return;
    int b = idx >> 9, e = idx & 511;
    const float* xp = g_xpre + ((size_t)s * BB + b) * GDIM;
    float gi = xp[e], gf = xp[EMBD + e], gg = xp[2 * EMBD + e], go = xp[3 * EMBD + e];
#pragma unroll
    for (int z = 0; z < KSPLIT; z++) {
        const float* pz = g_part + ((size_t)z * BB + b) * GDIM;
        gi += pz[e]; gf += pz[EMBD + e]; gg += pz[2 * EMBD + e]; go += pz[3 * EMBD + e];
    }
    float i_ = 1.f / (1.f + expf(-gi));
    float f_ = 1.f / (1.f + expf(-gf));
    float o_ = 1.f / (1.f + expf(-go));
    float g_ = tanhf(gg);
    float c  = f_ * g_c[idx] + i_ * g_;
    float h  = o_ * tanhf(c);
    g_c[idx] = c;
    g_h[idx] = h;
    g_seq[((size_t)b * TT + (s + 1)) * EMBD + e] = h;   // seq[:, s+1] = h_{s+1}
}

// ---------------- launch ----------------
extern "C" void kernel_launch(void* const* d_in, const int* in_sizes, int n_in,
                              void* d_out, int out_size) {
    const float* features = (const float*)d_in[0];
    const int*   captions = (const int*)d_in[1];
    const float* W_emb    = (const float*)d_in[2];
    const float* W_out    = (const float*)d_in[3];
    const float* b_out    = (const float*)d_in[4];
    const float* W_ih     = (const float*)d_in[5];
    const float* W_hh     = (const float*)d_in[6];
    const float* b_ih     = (const float*)d_in[7];
    const float* b_hh     = (const float*)d_in[8];
    float* out = (float*)d_out;
    (void)in_sizes; (void)n_in; (void)out_size;

    float *p_emb, *p_xpre, *p_part, *p_h, *p_seq;
    cudaGetSymbolAddress((void**)&p_emb,  g_embsteps);
    cudaGetSymbolAddress((void**)&p_xpre, g_xpre);
    cudaGetSymbolAddress((void**)&p_part, g_part);
    cudaGetSymbolAddress((void**)&p_h,    g_h);
    cudaGetSymbolAddress((void**)&p_seq,  g_seq);

    // 1) gather embeddings, init h0/c0, seq[:,0]
    init_kernel<<<(BB * TT * (EMBD / 4) + 255) / 256, 256>>>(features, captions, W_emb);

    // 2) xpre[t,b] = emb[t,b] @ W_ih^T + b_ih + b_hh   (3xTF32, fp32-grade)
    gemm_tf32<128, 4, 2, 2><<<dim3(GDIM / 128, (NSTEP * BB + 127) / 128, 1), 256>>>(
        p_emb, W_ih, p_xpre, b_ih, b_hh, NSTEP * BB, GDIM, EMBD);

    // 3) 19 recurrent steps: k-split gates GEMM (3xTF32) + pointwise cell
    for (int s = 0; s < NSTEP; s++) {
        gemm_tf32<64, 2, 4, 2><<<dim3(GDIM / 128, 1, KSPLIT), 256>>>(
            p_h, W_hh, p_part, nullptr, nullptr, BB, GDIM, EMBD / KSPLIT);
        cell_kernel<<<(BB * EMBD + 255) / 256, 256>>>(s);
    }

    // 4) logits = seq @ W_out^T + b_out   (single-pass TF32, ~4e-4 rel err)
    gemm_tf32<128, 4, 2, 1><<<dim3(VOC / 128, (BB * TT) / 128, 1), 256>>>(
        p_seq, W_out, out, b_out, nullptr, BB * TT, VOC, EMBD);
}

// round 4
// speedup vs baseline: 1.2816x; 1.2816x over previous
#include <cuda_runtime.h>
#include <cstdint>
#include <cstddef>

#define BB    64
#define TT    20
#define EMBD  512
#define VOC   32000
#define NSTEP 19
#define GDIM  2048
#define KSPLIT 8

// ---------------- scratch (no allocations allowed) ----------------
__device__ float g_embsteps[NSTEP * BB * EMBD];   // [t][b][e]
__device__ float g_seq[BB * TT * EMBD];           // [b][t][e]
__device__ float g_xpre[NSTEP * BB * GDIM];       // [t][b][4E]
__device__ float g_part[KSPLIT * BB * GDIM];      // k-split partials of h @ W_hh^T
__device__ float g_h[BB * EMBD];
__device__ float g_c[BB * EMBD];

// ---------------- helpers ----------------
__device__ __forceinline__ unsigned f2tf(float x) {
    unsigned u;
    asm("cvt.rna.tf32.f32 %0, %1;" : "=r"(u) : "f"(x));
    return u;
}

__device__ __forceinline__ void mma8(float c[4], const unsigned a[4], const unsigned b[2]) {
    asm volatile(
        "mma.sync.aligned.m16n8k8.row.col.f32.tf32.tf32.f32 "
        "{%0,%1,%2,%3}, {%4,%5,%6,%7}, {%8,%9}, {%0,%1,%2,%3};"
        : "+f"(c[0]), "+f"(c[1]), "+f"(c[2]), "+f"(c[3])
        : "r"(a[0]), "r"(a[1]), "r"(a[2]), "r"(a[3]), "r"(b[0]), "r"(b[1]));
}

// ---------------- init: embedding gather + h0/c0 ----------------
__global__ void init_kernel(const float* __restrict__ features,
                            const int*   __restrict__ captions,
                            const float* __restrict__ W_emb) {
    int idx = blockIdx.x * blockDim.x + threadIdx.x;       // over B*T*(E/4)
    if (idx >= BB * TT * (EMBD / 4)) return;
    int e4 = idx & (EMBD / 4 - 1);
    int bt = idx >> 7;
    int t = bt % TT, b = bt / TT;
    int cap = captions[b * TT + t];
    float4 v = *(const float4*)(W_emb + (size_t)cap * EMBD + e4 * 4);
    if (t < NSTEP)
        *(float4*)(g_embsteps + ((size_t)(t * BB + b)) * EMBD + e4 * 4) = v;
    if (t == 0) {
        *(float4*)(g_seq + ((size_t)b * TT) * EMBD + e4 * 4) = v;          // seq[:,0] = emb
        *(float4*)(g_h + (size_t)b * EMBD + e4 * 4) = make_float4(0.f, 0.f, 0.f, 0.f);
        *(float4*)(g_c + (size_t)b * EMBD + e4 * 4) =
            *(const float4*)(features + (size_t)b * EMBD + e4 * 4);        // c0 = features
    }
}

// ---------------- pipelined TF32 GEMM: C[M,N] = A[M,K] * B[N,K]^T (+bias) ----
// A, B row-major with row stride 512. Plain cp.async (16B), double-buffered,
// BK=8, static smem (<=48KB), EXACT tiles (no guards anywhere).
// Fragments tf32-converted in registers; NSPLIT=2 -> 3xTF32 accuracy.
// blockIdx.z: consumes K cols starting at z*K, writes C + z*M*N.
template <int BM, int BN, int WM, int WN, int NSPLIT, int THREADS>
__global__ void __launch_bounds__(THREADS)
gemm3(const float* __restrict__ A, const float* __restrict__ B,
      float* __restrict__ C,
      const float* __restrict__ bias0, const float* __restrict__ bias1,
      int M, int N, int K) {
    constexpr int BK = 8, LD = 12;            // LD=12: conflict-free, 16B-aligned rows
    constexpr int WROWS = BM / WM, WCOLS = BN / WN;
    constexpr int MT = WROWS / 16, NT = WCOLS / 8;
    static_assert(WM * WN == THREADS / 32, "warp grid");

    __shared__ float As[2 * BM * LD];
    __shared__ float Bs[2 * BN * LD];

    A += (size_t)blockIdx.z * K;
    B += (size_t)blockIdx.z * K;
    C += (size_t)blockIdx.z * M * N;

    const int tid = threadIdx.x, lane = tid & 31, w = tid >> 5;
    const int wm = w / WN, wn = w % WN;
    const int r = lane >> 2, cq = lane & 3;
    const int rowA0 = blockIdx.y * BM, rowB0 = blockIdx.x * BN;

    const uint32_t sA = (uint32_t)__cvta_generic_to_shared(As);
    const uint32_t sB = (uint32_t)__cvta_generic_to_shared(Bs);

    float acc[MT][NT][4] = {};

    auto stage = [&](int kt, int s) {
        for (int i = tid; i < BM * 2; i += THREADS) {
            int row = i >> 1, kq = i & 1;
            const float* src = A + (size_t)(rowA0 + row) * 512 + kt * BK + kq * 4;
            uint32_t dst = sA + (uint32_t)((s * BM + row) * LD + kq * 4) * 4;
            asm volatile("cp.async.cg.shared.global [%0], [%1], 16;\n"
                         :: "r"(dst), "l"(src));
        }
        for (int i = tid; i < BN * 2; i += THREADS) {
            int row = i >> 1, kq = i & 1;
            const float* src = B + (size_t)(rowB0 + row) * 512 + kt * BK + kq * 4;
            uint32_t dst = sB + (uint32_t)((s * BN + row) * LD + kq * 4) * 4;
            asm volatile("cp.async.cg.shared.global [%0], [%1], 16;\n"
                         :: "r"(dst), "l"(src));
        }
        asm volatile("cp.async.commit_group;\n");
    };

    const int KT = K / BK;
    stage(0, 0);
    for (int kt = 0; kt < KT; kt++) {
        const int s = kt & 1;
        if (kt + 1 < KT) {
            stage(kt + 1, s ^ 1);
            asm volatile("cp.async.wait_group 1;\n");
        } else {
            asm volatile("cp.async.wait_group 0;\n");
        }
        __syncthreads();

        const float* At = As + s * BM * LD;
        const float* Bt = Bs + s * BN * LD;

        unsigned ah[MT][4], al[MT][4];
#pragma unroll
        for (int mi = 0; mi < MT; mi++) {
            int m0 = wm * WROWS + mi * 16;
            float x0 = At[(m0 + r) * LD + cq];
            float x1 = At[(m0 + r + 8) * LD + cq];
            float x2 = At[(m0 + r) * LD + cq + 4];
            float x3 = At[(m0 + r + 8) * LD + cq + 4];
            ah[mi][0] = f2tf(x0); ah[mi][1] = f2tf(x1);
            ah[mi][2] = f2tf(x2); ah[mi][3] = f2tf(x3);
            if constexpr (NSPLIT == 2) {
                al[mi][0] = f2tf(x0 - __uint_as_float(ah[mi][0]));
                al[mi][1] = f2tf(x1 - __uint_as_float(ah[mi][1]));
                al[mi][2] = f2tf(x2 - __uint_as_float(ah[mi][2]));
                al[mi][3] = f2tf(x3 - __uint_as_float(ah[mi][3]));
            }
        }
#pragma unroll
        for (int ni = 0; ni < NT; ni++) {
            int n0 = wn * WCOLS + ni * 8;
            float y0 = Bt[(n0 + r) * LD + cq];
            float y1 = Bt[(n0 + r) * LD + cq + 4];
            unsigned bh[2] = {f2tf(y0), f2tf(y1)};
            unsigned bl[2];
            if constexpr (NSPLIT == 2) {
                bl[0] = f2tf(y0 - __uint_as_float(bh[0]));
                bl[1] = f2tf(y1 - __uint_as_float(bh[1]));
            }
#pragma unroll
            for (int mi = 0; mi < MT; mi++) {
                mma8(acc[mi][ni], ah[mi], bh);
                if constexpr (NSPLIT == 2) {
                    mma8(acc[mi][ni], ah[mi], bl);
                    mma8(acc[mi][ni], al[mi], bh);
                }
            }
        }
        __syncthreads();
    }

    // epilogue (tiles are exact: no guards)
#pragma unroll
    for (int mi = 0; mi < MT; mi++) {
        const int row0 = rowA0 + wm * WROWS + mi * 16 + r;
#pragma unroll
        for (int ni = 0; ni < NT; ni++) {
            const int col = rowB0 + wn * WCOLS + ni * 8 + 2 * cq;
            float b0 = 0.f, b1 = 0.f;
            if (bias0) { b0 += bias0[col]; b1 += bias0[col + 1]; }
            if (bias1) { b0 += bias1[col]; b1 += bias1[col + 1]; }
            float2 o0, o1;
            o0.x = acc[mi][ni][0] + b0;
            o0.y = acc[mi][ni][1] + b1;
            o1.x = acc[mi][ni][2] + b0;
            o1.y = acc[mi][ni][3] + b1;
            *(float2*)(C + (size_t)row0 * N + col) = o0;
            *(float2*)(C + (size_t)(row0 + 8) * N + col) = o1;
        }
    }
}

// ---------------- LSTM cell pointwise (float4) ----------------
__device__ __forceinline__ float4 f4add(float4 a, float4 b) {
    return make_float4(a.x + b.x, a.y + b.y, a.z + b.z, a.w + b.w);
}
__device__ __forceinline__ float fsig(float x) { return 1.f / (1.f + __expf(-x)); }
__device__ __forceinline__ float ftanh(float x) {
    float e = __expf(-2.f * x);
    return (1.f - e) / (1.f + e);
}

__global__ void cell_kernel(int s) {
    int idx = blockIdx.x * blockDim.x + threadIdx.x;   // over BB * (EMBD/4) = 8192
    if (idx >= BB * (EMBD / 4)) return;
    int b = idx >> 7, e4 = idx & 127;
    const float4* xp = (const float4*)(g_xpre + ((size_t)s * BB + b) * GDIM);
    float4 gi = xp[e4], gf = xp[128 + e4], gg = xp[256 + e4], go = xp[384 + e4];
#pragma unroll
    for (int z = 0; z < KSPLIT; z++) {
        const float4* pz = (const float4*)(g_part + ((size_t)z * BB + b) * GDIM);
        gi = f4add(gi, pz[e4]);
        gf = f4add(gf, pz[128 + e4]);
        gg = f4add(gg, pz[256 + e4]);
        go = f4add(go, pz[384 + e4]);
    }
    float4 cold = *(const float4*)(g_c + idx * 4);
    float4 cn, hn;
    cn.x = fsig(gf.x) * cold.x + fsig(gi.x) * ftanh(gg.x);
    cn.y = fsig(gf.y) * cold.y + fsig(gi.y) * ftanh(gg.y);
    cn.z = fsig(gf.z) * cold.z + fsig(gi.z) * ftanh(gg.z);
    cn.w = fsig(gf.w) * cold.w + fsig(gi.w) * ftanh(gg.w);
    hn.x = fsig(go.x) * ftanh(cn.x);
    hn.y = fsig(go.y) * ftanh(cn.y);
    hn.z = fsig(go.z) * ftanh(cn.z);
    hn.w = fsig(go.w) * ftanh(cn.w);
    *(float4*)(g_c + idx * 4) = cn;
    *(float4*)(g_h + idx * 4) = hn;
    *(float4*)(g_seq + ((size_t)b * TT + (s + 1)) * EMBD + e4 * 4) = hn;
}

// ---------------- launch ----------------
extern "C" void kernel_launch(void* const* d_in, const int* in_sizes, int n_in,
                              void* d_out, int out_size) {
    const float* features = (const float*)d_in[0];
    const int*   captions = (const int*)d_in[1];
    const float* W_emb    = (const float*)d_in[2];
    const float* W_out    = (const float*)d_in[3];
    const float* b_out    = (const float*)d_in[4];
    const float* W_ih     = (const float*)d_in[5];
    const float* W_hh     = (const float*)d_in[6];
    const float* b_ih     = (const float*)d_in[7];
    const float* b_hh     = (const float*)d_in[8];
    float* out = (float*)d_out;
    (void)in_sizes; (void)n_in; (void)out_size;

    float *p_emb, *p_xpre, *p_part, *p_h, *p_seq;
    cudaGetSymbolAddress((void**)&p_emb,  g_embsteps);
    cudaGetSymbolAddress((void**)&p_xpre, g_xpre);
    cudaGetSymbolAddress((void**)&p_part, g_part);
    cudaGetSymbolAddress((void**)&p_h,    g_h);
    cudaGetSymbolAddress((void**)&p_seq,  g_seq);

    // 1) gather embeddings, init h0/c0, seq[:,0]
    init_kernel<<<(BB * TT * (EMBD / 4) + 255) / 256, 256>>>(features, captions, W_emb);

    // 2) xpre = emb @ W_ih^T + b_ih + b_hh   (3xTF32; M=1216=19*64 exact)
    gemm3<64, 128, 2, 4, 2, 256><<<dim3(GDIM / 128, NSTEP * BB / 64, 1), 256>>>(
        p_emb, W_ih, p_xpre, b_ih, b_hh, NSTEP * BB, GDIM, EMBD);

    // 3) 19 recurrent steps: 8-way k-split gates GEMM (3xTF32) + fused cell
    for (int s = 0; s < NSTEP; s++) {
        gemm3<64, 128, 2, 4, 2, 256><<<dim3(GDIM / 128, 1, KSPLIT), 256>>>(
            p_h, W_hh, p_part, nullptr, nullptr, BB, GDIM, EMBD / KSPLIT);
        cell_kernel<<<BB * (EMBD / 4) / 256, 256>>>(s);
    }

    // 4) logits = seq @ W_out^T + b_out   (single-pass TF32; M=1280=10*128 exact)
    gemm3<128, 256, 4, 4, 1, 512><<<dim3(VOC / 256, BB * TT / 128, 1), 512>>>(
        p_seq, W_out, out, b_out, nullptr, BB * TT, VOC, EMBD);
}

// round 7
// speedup vs baseline: 1.3048x; 1.0181x over previous
#include <cuda_runtime.h>
#include <cstdint>
#include <cstddef>

#define BB    64
#define TT    20
#define EMBD  512
#define VOC   32000
#define NSTEP 19
#define GDIM  2048
#define ETILE 4
#define NTILE 16            // 4 gates * ETILE
#define NCTA  (EMBD / ETILE) // 128 step-kernel CTAs

// ---------------- scratch (no allocations allowed) ----------------
__device__ float g_embsteps[NSTEP * BB * EMBD];   // [t][b][e]
__device__ float g_seq[BB * TT * EMBD];           // [b][t][e]
__device__ float g_xpre[NSTEP * BB * GDIM];       // [t][b][4E]
__device__ float g_h[BB * EMBD];
__device__ float g_c[BB * EMBD];

// ---------------- helpers ----------------
__device__ __forceinline__ unsigned f2tf(float x) {
    unsigned u;
    asm("cvt.rna.tf32.f32 %0, %1;" : "=r"(u) : "f"(x));
    return u;
}

__device__ __forceinline__ void mma8(float c[4], const unsigned a[4], const unsigned b[2]) {
    asm volatile(
        "mma.sync.aligned.m16n8k8.row.col.f32.tf32.tf32.f32 "
        "{%0,%1,%2,%3}, {%4,%5,%6,%7}, {%8,%9}, {%0,%1,%2,%3};"
        : "+f"(c[0]), "+f"(c[1]), "+f"(c[2]), "+f"(c[3])
        : "r"(a[0]), "r"(a[1]), "r"(a[2]), "r"(a[3]), "r"(b[0]), "r"(b[1]));
}

__device__ __forceinline__ float fsig(float x) { return 1.f / (1.f + __expf(-x)); }
__device__ __forceinline__ float ftanh(float x) {
    float e = __expf(-2.f * x);
    return (1.f - e) / (1.f + e);
}

// ---------------- init: embedding gather + h0/c0 ----------------
__global__ void init_kernel(const float* __restrict__ features,
                            const int*   __restrict__ captions,
                            const float* __restrict__ W_emb) {
    int idx = blockIdx.x * blockDim.x + threadIdx.x;       // over B*T*(E/4)
    if (idx >= BB * TT * (EMBD / 4)) return;
    int e4 = idx & (EMBD / 4 - 1);
    int bt = idx >> 7;
    int t = bt % TT, b = bt / TT;
    int cap = captions[b * TT + t];
    float4 v = *(const float4*)(W_emb + (size_t)cap * EMBD + e4 * 4);
    if (t < NSTEP)
        *(float4*)(g_embsteps + ((size_t)(t * BB + b)) * EMBD + e4 * 4) = v;
    if (t == 0) {
        *(float4*)(g_seq + ((size_t)b * TT) * EMBD + e4 * 4) = v;          // seq[:,0] = emb
        *(float4*)(g_h + (size_t)b * EMBD + e4 * 4) = make_float4(0.f, 0.f, 0.f, 0.f);
        *(float4*)(g_c + (size_t)b * EMBD + e4 * 4) =
            *(const float4*)(features + (size_t)b * EMBD + e4 * 4);        // c0 = features
    }
}

// ---------------- pipelined TF32 GEMM: C[M,N] = A[M,K] * B[N,K]^T (+bias) ----
// (used for xpre precompute and the output projection; exact tiles, no guards)
template <int BM, int BN, int WM, int WN, int NSPLIT, int THREADS>
__global__ void __launch_bounds__(THREADS)
gemm3(const float* __restrict__ A, const float* __restrict__ B,
      float* __restrict__ C,
      const float* __restrict__ bias0, const float* __restrict__ bias1,
      int M, int N, int K) {
    constexpr int BK = 8, LD = 12;
    constexpr int WROWS = BM / WM, WCOLS = BN / WN;
    constexpr int MT = WROWS / 16, NT = WCOLS / 8;
    static_assert(WM * WN == THREADS / 32, "warp grid");

    __shared__ float As[2 * BM * LD];
    __shared__ float Bs[2 * BN * LD];

    const int tid = threadIdx.x, lane = tid & 31, w = tid >> 5;
    const int wm = w / WN, wn = w % WN;
    const int r = lane >> 2, cq = lane & 3;
    const int rowA0 = blockIdx.y * BM, rowB0 = blockIdx.x * BN;

    const uint32_t sA = (uint32_t)__cvta_generic_to_shared(As);
    const uint32_t sB = (uint32_t)__cvta_generic_to_shared(Bs);

    float acc[MT][NT][4] = {};

    auto stage = [&](int kt, int s) {
        for (int i = tid; i < BM * 2; i += THREADS) {
            int row = i >> 1, kq = i & 1;
            const float* src = A + (size_t)(rowA0 + row) * 512 + kt * BK + kq * 4;
            uint32_t dst = sA + (uint32_t)((s * BM + row) * LD + kq * 4) * 4;
            asm volatile("cp.async.cg.shared.global [%0], [%1], 16;\n"
                         :: "r"(dst), "l"(src));
        }
        for (int i = tid; i < BN * 2; i += THREADS) {
            int row = i >> 1, kq = i & 1;
            const float* src = B + (size_t)(rowB0 + row) * 512 + kt * BK + kq * 4;
            uint32_t dst = sB + (uint32_t)((s * BN + row) * LD + kq * 4) * 4;
            asm volatile("cp.async.cg.shared.global [%0], [%1], 16;\n"
                         :: "r"(dst), "l"(src));
        }
        asm volatile("cp.async.commit_group;\n");
    };

    const int KT = K / BK;
    stage(0, 0);
    for (int kt = 0; kt < KT; kt++) {
        const int s = kt & 1;
        if (kt + 1 < KT) {
            stage(kt + 1, s ^ 1);
            asm volatile("cp.async.wait_group 1;\n");
        } else {
            asm volatile("cp.async.wait_group 0;\n");
        }
        __syncthreads();

        const float* At = As + s * BM * LD;
        const float* Bt = Bs + s * BN * LD;

        unsigned ah[MT][4], al[MT][4];
#pragma unroll
        for (int mi = 0; mi < MT; mi++) {
            int m0 = wm * WROWS + mi * 16;
            float x0 = At[(m0 + r) * LD + cq];
            float x1 = At[(m0 + r + 8) * LD + cq];
            float x2 = At[(m0 + r) * LD + cq + 4];
            float x3 = At[(m0 + r + 8) * LD + cq + 4];
            ah[mi][0] = f2tf(x0); ah[mi][1] = f2tf(x1);
            ah[mi][2] = f2tf(x2); ah[mi][3] = f2tf(x3);
            if constexpr (NSPLIT == 2) {
                al[mi][0] = f2tf(x0 - __uint_as_float(ah[mi][0]));
                al[mi][1] = f2tf(x1 - __uint_as_float(ah[mi][1]));
                al[mi][2] = f2tf(x2 - __uint_as_float(ah[mi][2]));
                al[mi][3] = f2tf(x3 - __uint_as_float(ah[mi][3]));
            }
        }
#pragma unroll
        for (int ni = 0; ni < NT; ni++) {
            int n0 = wn * WCOLS + ni * 8;
            float y0 = Bt[(n0 + r) * LD + cq];
            float y1 = Bt[(n0 + r) * LD + cq + 4];
            unsigned bh[2] = {f2tf(y0), f2tf(y1)};
            unsigned bl[2];
            if constexpr (NSPLIT == 2) {
                bl[0] = f2tf(y0 - __uint_as_float(bh[0]));
                bl[1] = f2tf(y1 - __uint_as_float(bh[1]));
            }
#pragma unroll
            for (int mi = 0; mi < MT; mi++) {
                mma8(acc[mi][ni], ah[mi], bh);
                if constexpr (NSPLIT == 2) {
                    mma8(acc[mi][ni], ah[mi], bl);
                    mma8(acc[mi][ni], al[mi], bh);
                }
            }
        }
        __syncthreads();
    }

#pragma unroll
    for (int mi = 0; mi < MT; mi++) {
        const int row0 = rowA0 + wm * WROWS + mi * 16 + r;
#pragma unroll
        for (int ni = 0; ni < NT; ni++) {
            const int col = rowB0 + wn * WCOLS + ni * 8 + 2 * cq;
            float b0 = 0.f, b1 = 0.f;
            if (bias0) { b0 += bias0[col]; b1 += bias0[col + 1]; }
            if (bias1) { b0 += bias1[col]; b1 += bias1[col + 1]; }
            float2 o0, o1;
            o0.x = acc[mi][ni][0] + b0;
            o0.y = acc[mi][ni][1] + b1;
            o1.x = acc[mi][ni][2] + b0;
            o1.y = acc[mi][ni][3] + b1;
            *(float2*)(C + (size_t)row0 * N + col) = o0;
            *(float2*)(C + (size_t)(row0 + 8) * N + col) = o1;
        }
    }
}

// ---------------- fused LSTM step: gates tile + cell, no gmem partials ------
// CTA c owns e in [4c, 4c+4). Gate tile: 64 batches x 16 cols, where
// col n = q*4 + j  ->  gate q of e = 4c + j  ->  W_hh row q*512 + 4c + j.
// 8 warps = 4 K-groups (128 each) x 2 n-halves; smem reduction over K-groups;
// then 256 threads apply the LSTM cell pointwise and write h/c/seq.
__global__ void __launch_bounds__(256)
step_kernel(const float* __restrict__ W_hh, int s) {
    constexpr int LD = 12;
    __shared__ float As[2][4][64][LD];      // 24 KB  (h chunks per K-group)
    __shared__ float Bs[2][4][NTILE][LD];   //  6 KB  (W_hh rows per K-group)
    __shared__ float P[4][64][NTILE];       // 16 KB  (per-K-group partials)

    const int c = blockIdx.x;
    const int tid = threadIdx.x, lane = tid & 31, w = tid >> 5;
    const int kg = w >> 1, nh = w & 1;
    const int r = lane >> 2, cq = lane & 3;

    const uint32_t sA = (uint32_t)__cvta_generic_to_shared(&As[0][0][0][0]);
    const uint32_t sB = (uint32_t)__cvta_generic_to_shared(&Bs[0][0][0][0]);

    auto stage = [&](int kt, int st) {
        // h chunks: 4 kg * 64 rows * 2 halves (16B each)
        for (int i = tid; i < 512; i += 256) {
            int g = i >> 7, rem = i & 127, row = rem >> 1, half = rem & 1;
            const float* src = g_h + row * 512 + g * 128 + kt * 8 + half * 4;
            uint32_t dst = sA + (uint32_t)(((st * 4 + g) * 64 + row) * LD + half * 4) * 4;
            asm volatile("cp.async.cg.shared.global [%0], [%1], 16;\n"
                         :: "r"(dst), "l"(src));
        }
        // W_hh rows: 4 kg * 16 rows * 2 halves
        for (int i = tid; i < 128; i += 256) {
            int g = i >> 5, rem = i & 31, row = rem >> 1, half = rem & 1;
            int grow = (row >> 2) * 512 + c * ETILE + (row & 3);
            const float* src = W_hh + (size_t)grow * 512 + g * 128 + kt * 8 + half * 4;
            uint32_t dst = sB + (uint32_t)(((st * 4 + g) * NTILE + row) * LD + half * 4) * 4;
            asm volatile("cp.async.cg.shared.global [%0], [%1], 16;\n"
                         :: "r"(dst), "l"(src));
        }
        asm volatile("cp.async.commit_group;\n");
    };

    float acc[4][4] = {};   // 4 m-tiles x one 8-col n-tile

    stage(0, 0);
    for (int kt = 0; kt < 16; kt++) {       // 128 K per group / BK=8
        const int st = kt & 1;
        if (kt + 1 < 16) {
            stage(kt + 1, st ^ 1);
            asm volatile("cp.async.wait_group 1;\n");
        } else {
            asm volatile("cp.async.wait_group 0;\n");
        }
        __syncthreads();

        const float (*At)[LD] = As[st][kg];
        const float (*Bt)[LD] = Bs[st][kg];

        float y0 = Bt[nh * 8 + r][cq];
        float y1 = Bt[nh * 8 + r][cq + 4];
        unsigned bh[2] = {f2tf(y0), f2tf(y1)};
        unsigned bl[2] = {f2tf(y0 - __uint_as_float(bh[0])),
                          f2tf(y1 - __uint_as_float(bh[1]))};
#pragma unroll
        for (int mi = 0; mi < 4; mi++) {
            int m0 = mi * 16;
            float x0 = At[m0 + r][cq];
            float x1 = At[m0 + r + 8][cq];
            float x2 = At[m0 + r][cq + 4];
            float x3 = At[m0 + r + 8][cq + 4];
            unsigned ah[4] = {f2tf(x0), f2tf(x1), f2tf(x2), f2tf(x3)};
            unsigned al[4] = {f2tf(x0 - __uint_as_float(ah[0])),
                              f2tf(x1 - __uint_as_float(ah[1])),
                              f2tf(x2 - __uint_as_float(ah[2])),
                              f2tf(x3 - __uint_as_float(ah[3]))};
            mma8(acc[mi], ah, bh);
            mma8(acc[mi], ah, bl);
            mma8(acc[mi], al, bh);
        }
        __syncthreads();
    }

    // write per-K-group partials
#pragma unroll
    for (int mi = 0; mi < 4; mi++) {
        int row = mi * 16 + r;
        int col = nh * 8 + 2 * cq;
        P[kg][row][col]     = acc[mi][0];
        P[kg][row][col + 1] = acc[mi][1];
        P[kg][row + 8][col]     = acc[mi][2];
        P[kg][row + 8][col + 1] = acc[mi][3];
    }
    __syncthreads();

    // cell: thread -> (batch b, e-offset j)
    {
        int b = tid >> 2, j = tid & 3;
        int e = c * ETILE + j;
        const float* xp = g_xpre + ((size_t)s * BB + b) * GDIM;
        float gi = xp[e]            + P[0][b][j]      + P[1][b][j]      + P[2][b][j]      + P[3][b][j];
        float gf = xp[512 + e]      + P[0][b][4 + j]  + P[1][b][4 + j]  + P[2][b][4 + j]  + P[3][b][4 + j];
        float gg = xp[1024 + e]     + P[0][b][8 + j]  + P[1][b][8 + j]  + P[2][b][8 + j]  + P[3][b][8 + j];
        float go = xp[1536 + e]     + P[0][b][12 + j] + P[1][b][12 + j] + P[2][b][12 + j] + P[3][b][12 + j];
        float cold = g_c[b * EMBD + e];
        float cn = fsig(gf) * cold + fsig(gi) * ftanh(gg);
        float hn = fsig(go) * ftanh(cn);
        g_c[b * EMBD + e] = cn;
        g_h[b * EMBD + e] = hn;
        g_seq[((size_t)b * TT + (s + 1)) * EMBD + e] = hn;
    }
}

// ---------------- launch ----------------
extern "C" void kernel_launch(void* const* d_in, const int* in_sizes, int n_in,
                              void* d_out, int out_size) {
    const float* features = (const float*)d_in[0];
    const int*   captions = (const int*)d_in[1];
    const float* W_emb    = (const float*)d_in[2];
    const float* W_out    = (const float*)d_in[3];
    const float* b_out    = (const float*)d_in[4];
    const float* W_ih     = (const float*)d_in[5];
    const float* W_hh     = (const float*)d_in[6];
    const float* b_ih     = (const float*)d_in[7];
    const float* b_hh     = (const float*)d_in[8];
    float* out = (float*)d_out;
    (void)in_sizes; (void)n_in; (void)out_size;

    float *p_emb, *p_xpre, *p_seq;
    cudaGetSymbolAddress((void**)&p_emb,  g_embsteps);
    cudaGetSymbolAddress((void**)&p_xpre, g_xpre);
    cudaGetSymbolAddress((void**)&p_seq,  g_seq);

    // 1) gather embeddings, init h0/c0, seq[:,0]
    init_kernel<<<(BB * TT * (EMBD / 4) + 255) / 256, 256>>>(features, captions, W_emb);

    // 2) xpre = emb @ W_ih^T + b_ih + b_hh   (3xTF32; M=1216=19*64 exact)
    gemm3<64, 128, 2, 4, 2, 256><<<dim3(GDIM / 128, NSTEP * BB / 64, 1), 256>>>(
        p_emb, W_ih, p_xpre, b_ih, b_hh, NSTEP * BB, GDIM, EMBD);

    // 3) 19 fused recurrent steps (gates mma + cell in one kernel, no partials)
    for (int s = 0; s < NSTEP; s++)
        step_kernel<<<NCTA, 256>>>(W_hh, s);

    // 4) logits = seq @ W_out^T + b_out   (single-pass TF32; M=1280=10*128 exact)
    gemm3<128, 256, 4, 4, 1, 512><<<dim3(VOC / 256, BB * TT / 128, 1), 512>>>(
        p_seq, W_out, out, b_out, nullptr, BB * TT, VOC, EMBD);
}